// round 3
// baseline (speedup 1.0000x reference)
#include <cuda_runtime.h>
#include <cuda_bf16.h>
#include <math.h>
#include <stdint.h>

#define BATCH     1024
#define NF        256
#define NS        100000
#define INV_TEMP  20.0f
#define NTILE     128
#define NBLK      ((NS + NTILE - 1) / NTILE)   /* 782 */
#define MCHUNK    128
#define NCHUNKS   (BATCH / MCHUNK)             /* 8 */
#define LDSS      264                          /* 256 + 8 bf16 pad: conflict-free ldmatrix */

#define SM_A      0
#define SM_B      (MCHUNK * LDSS * 2)                 /* 67584 */
#define SM_RED_M  (SM_B + NTILE * LDSS * 2)           /* 135168 */
#define SM_RED_S  (SM_RED_M + 4 * 128 * 4)
#define SMEM_BYTES (SM_RED_S + 4 * 128 * 4 + 64)

__device__ __nv_bfloat16 g_a_bf16[BATCH * NF];
__device__ float g_pm[(size_t)NBLK * BATCH];
__device__ float g_ps[(size_t)NBLK * BATCH];
__device__ float g_tlogit[BATCH];
__device__ float g_rownll[BATCH];
__device__ int   g_tstride;

// ---------------------------------------------------------------- helpers
__device__ __forceinline__ uint32_t sptr(const void* p) {
    return (uint32_t)__cvta_generic_to_shared(p);
}
__device__ __forceinline__ void ldsm4(uint32_t addr, uint32_t& r0, uint32_t& r1,
                                      uint32_t& r2, uint32_t& r3) {
    asm volatile("ldmatrix.sync.aligned.m8n8.x4.shared.b16 {%0,%1,%2,%3}, [%4];"
                 : "=r"(r0), "=r"(r1), "=r"(r2), "=r"(r3) : "r"(addr));
}
__device__ __forceinline__ void mma16816(float c[4], const uint32_t a[4],
                                         uint32_t b0, uint32_t b1) {
    asm volatile(
        "mma.sync.aligned.m16n8k16.row.col.f32.bf16.bf16.f32 "
        "{%0,%1,%2,%3},{%4,%5,%6,%7},{%8,%9},{%0,%1,%2,%3};"
        : "+f"(c[0]), "+f"(c[1]), "+f"(c[2]), "+f"(c[3])
        : "r"(a[0]), "r"(a[1]), "r"(a[2]), "r"(a[3]), "r"(b0), "r"(b1));
}

// ---------------------------------------------------------------- prep kernels
__global__ void prep_kernel(const float* __restrict__ a) {
    int i = blockIdx.x * blockDim.x + threadIdx.x;
    if (i < BATCH * NF) g_a_bf16[i] = __float2bfloat16(a[i]);
}

// targets may be int64 or int32; detect within first 2KB (safe either way)
__global__ void detect_kernel(const int* __restrict__ t32) {
    if (threadIdx.x == 0 && blockIdx.x == 0) {
        int s = 2;
        for (int i = 1; i < 512; i += 2)
            if (t32[i] != 0) { s = 1; break; }
        g_tstride = s;
    }
}

// exact fp32 target logit per row
__global__ void tlogit_kernel(const float* __restrict__ a,
                              const int* __restrict__ t32,
                              const float* __restrict__ f) {
    int row = blockIdx.x;
    int tid = threadIdx.x;  // 256
    long long tgt = (long long)t32[row * g_tstride];
    float p = a[row * NF + tid] * f[tgt * NF + tid];
    for (int off = 16; off; off >>= 1) p += __shfl_xor_sync(~0u, p, off);
    __shared__ float sm[8];
    if ((tid & 31) == 0) sm[tid >> 5] = p;
    __syncthreads();
    if (tid == 0) {
        float s = 0.f;
        #pragma unroll
        for (int w = 0; w < 8; w++) s += sm[w];
        g_tlogit[row] = s * INV_TEMP;
    }
}

// ---------------------------------------------------------------- fused GEMM + online softmax partials
extern __shared__ char smem_raw[];

__global__ void __launch_bounds__(512, 1) gemm_lse_kernel(const float* __restrict__ feats) {
    __nv_bfloat16* As = (__nv_bfloat16*)(smem_raw + SM_A);   // [128][264]
    __nv_bfloat16* Bs = (__nv_bfloat16*)(smem_raw + SM_B);   // [128][264]
    float* red_m = (float*)(smem_raw + SM_RED_M);            // [4][128]
    float* red_s = (float*)(smem_raw + SM_RED_S);            // [4][128]

    const int tid  = threadIdx.x;
    const int lane = tid & 31, warp = tid >> 5;     // 16 warps
    const int wm = warp & 3, wn = warp >> 2;        // 4x4 warp grid, 32x32 tiles
    const int nbase = blockIdx.x * NTILE;

    // Load feature slab once (fp32 -> bf16)
    for (int i = tid; i < NTILE * (NF / 4); i += 512) {
        int r  = i >> 6;        // 64 float4 per row
        int c4 = i & 63;
        int srow = nbase + r;
        float4 v = make_float4(0.f, 0.f, 0.f, 0.f);
        if (srow < NS) v = ((const float4*)feats)[(size_t)srow * (NF / 4) + c4];
        __nv_bfloat162 p0 = __floats2bfloat162_rn(v.x, v.y);
        __nv_bfloat162 p1 = __floats2bfloat162_rn(v.z, v.w);
        uint2 u;
        u.x = *(uint32_t*)&p0;
        u.y = *(uint32_t*)&p1;
        *(uint2*)(Bs + r * LDSS + c4 * 4) = u;
    }

    const int aRow = lane & 15,                       aKo = (lane >> 4) << 3;
    const int bRow = (lane & 7) + ((lane >> 4) << 3), bKo = ((lane >> 3) & 1) << 3;
    const int qr = lane >> 2, qc = lane & 3;

    #pragma unroll 1
    for (int mc = 0; mc < NCHUNKS; mc++) {
        __syncthreads();
        // A chunk (bf16, L2-resident) -> SMEM
        for (int i = tid; i < MCHUNK * (NF / 8); i += 512) {
            int r  = i >> 5;    // 32 uint4 per row
            int c8 = i & 31;
            uint4 v = ((const uint4*)g_a_bf16)[(size_t)(mc * MCHUNK + r) * (NF / 8) + c8];
            *(uint4*)(As + r * LDSS + c8 * 8) = v;
        }
        __syncthreads();

        float acc[2][4][4];
        #pragma unroll
        for (int mf = 0; mf < 2; mf++)
            #pragma unroll
            for (int nf = 0; nf < 4; nf++)
                #pragma unroll
                for (int j = 0; j < 4; j++) acc[mf][nf][j] = 0.f;

        #pragma unroll 4
        for (int kk = 0; kk < NF; kk += 16) {
            uint32_t afrag[2][4];
            #pragma unroll
            for (int mf = 0; mf < 2; mf++) {
                uint32_t addr = sptr(As + (wm * 32 + mf * 16 + aRow) * LDSS + kk + aKo);
                ldsm4(addr, afrag[mf][0], afrag[mf][1], afrag[mf][2], afrag[mf][3]);
            }
            uint32_t bfrag[4][2];
            #pragma unroll
            for (int np = 0; np < 2; np++) {
                uint32_t addr = sptr(Bs + (wn * 32 + np * 16 + bRow) * LDSS + kk + bKo);
                uint32_t r0, r1, r2, r3;
                ldsm4(addr, r0, r1, r2, r3);
                bfrag[np * 2][0]     = r0;  bfrag[np * 2][1]     = r1;
                bfrag[np * 2 + 1][0] = r2;  bfrag[np * 2 + 1][1] = r3;
            }
            #pragma unroll
            for (int mf = 0; mf < 2; mf++)
                #pragma unroll
                for (int nf = 0; nf < 4; nf++)
                    mma16816(acc[mf][nf], afrag[mf], bfrag[nf][0], bfrag[nf][1]);
        }

        // per-row online-softmax partials over this warp's 32-col slice
        #pragma unroll
        for (int mf = 0; mf < 2; mf++) {
            #pragma unroll
            for (int hi = 0; hi < 2; hi++) {
                float m = -INFINITY;
                #pragma unroll
                for (int nf = 0; nf < 4; nf++)
                    #pragma unroll
                    for (int j = 0; j < 2; j++) {
                        int cg = nbase + wn * 32 + nf * 8 + qc * 2 + j;
                        float v = acc[mf][nf][hi * 2 + j] * INV_TEMP;
                        if (cg < NS) m = fmaxf(m, v);
                    }
                m = fmaxf(m, __shfl_xor_sync(~0u, m, 1));
                m = fmaxf(m, __shfl_xor_sync(~0u, m, 2));
                float s = 0.f;
                #pragma unroll
                for (int nf = 0; nf < 4; nf++)
                    #pragma unroll
                    for (int j = 0; j < 2; j++) {
                        int cg = nbase + wn * 32 + nf * 8 + qc * 2 + j;
                        float v = acc[mf][nf][hi * 2 + j] * INV_TEMP;
                        if (cg < NS) s += __expf(v - m);
                    }
                s += __shfl_xor_sync(~0u, s, 1);
                s += __shfl_xor_sync(~0u, s, 2);
                if (qc == 0) {
                    int rl = wm * 32 + mf * 16 + hi * 8 + qr;
                    red_m[wn * 128 + rl] = m;
                    red_s[wn * 128 + rl] = s;
                }
            }
        }
        __syncthreads();
        if (tid < 128) {
            float M = red_m[tid];                 // wn=0 slice always has valid cols
            #pragma unroll
            for (int w = 1; w < 4; w++) M = fmaxf(M, red_m[w * 128 + tid]);
            float S = 0.f;
            #pragma unroll
            for (int w = 0; w < 4; w++)
                S += red_s[w * 128 + tid] * __expf(red_m[w * 128 + tid] - M);
            int grow = mc * MCHUNK + tid;
            g_pm[(size_t)blockIdx.x * BATCH + grow] = M;
            g_ps[(size_t)blockIdx.x * BATCH + grow] = S;
        }
    }
}

// ---------------------------------------------------------------- cross-block LSE merge
__global__ void lse_kernel() {
    int row = blockIdx.x;
    int tid = threadIdx.x;  // 256
    float M = -INFINITY, S = 0.f;
    for (int b = tid; b < NBLK; b += 256) {
        float m = g_pm[(size_t)b * BATCH + row];
        float s = g_ps[(size_t)b * BATCH + row];
        float nM = fmaxf(M, m);
        S = S * __expf(M - nM) + s * __expf(m - nM);
        M = nM;
    }
    for (int off = 16; off; off >>= 1) {
        float m = __shfl_xor_sync(~0u, M, off);
        float s = __shfl_xor_sync(~0u, S, off);
        float nM = fmaxf(M, m);
        S = S * __expf(M - nM) + s * __expf(m - nM);
        M = nM;
    }
    __shared__ float sm[8], ss[8];
    int w = tid >> 5, ln = tid & 31;
    if (ln == 0) { sm[w] = M; ss[w] = S; }
    __syncthreads();
    if (tid == 0) {
        float Mv = sm[0], Sv = ss[0];
        #pragma unroll
        for (int i = 1; i < 8; i++) {
            float m = sm[i], s = ss[i];
            float nM = fmaxf(Mv, m);
            Sv = Sv * __expf(Mv - nM) + s * __expf(m - nM);
            Mv = nM;
        }
        g_rownll[row] = Mv + logf(Sv) - g_tlogit[row];
    }
}

__global__ void mean_kernel(float* __restrict__ out) {
    __shared__ float sm[32];
    int tid = threadIdx.x;  // 1024
    float v = g_rownll[tid];
    for (int off = 16; off; off >>= 1) v += __shfl_xor_sync(~0u, v, off);
    if ((tid & 31) == 0) sm[tid >> 5] = v;
    __syncthreads();
    if (tid < 32) {
        float x = sm[tid];
        for (int off = 16; off; off >>= 1) x += __shfl_xor_sync(~0u, x, off);
        if (tid == 0) out[0] = x / (float)BATCH;
    }
}

// ---------------------------------------------------------------- launch
extern "C" void kernel_launch(void* const* d_in, const int* in_sizes, int n_in,
                              void* d_out, int out_size) {
    const float* a   = (const float*)d_in[0];   // inputs   [1024,256] f32
    const int*   t32 = (const int*)d_in[1];     // targets  [1024] i64/i32
    const float* f   = (const float*)d_in[2];   // features [100000,256] f32
    float* out = (float*)d_out;

    cudaFuncSetAttribute(gemm_lse_kernel,
                         cudaFuncAttributeMaxDynamicSharedMemorySize, SMEM_BYTES);

    prep_kernel<<<(BATCH * NF + 255) / 256, 256>>>(a);
    detect_kernel<<<1, 32>>>(t32);
    tlogit_kernel<<<BATCH, 256>>>(a, t32, f);
    gemm_lse_kernel<<<NBLK, 512, SMEM_BYTES>>>(f);
    lse_kernel<<<BATCH, 256>>>();
    mean_kernel<<<1, 1024>>>(out);
}

// round 4
// speedup vs baseline: 1.0845x; 1.0845x over previous
#include <cuda_runtime.h>
#include <cuda_bf16.h>
#include <math.h>
#include <stdint.h>

#define BATCH     1024
#define NF        256
#define NS        100000
#define INV_TEMP  20.0f
#define NTILE     128
#define NBLK      ((NS + NTILE - 1) / NTILE)   /* 782 */
#define MCHUNK    128
#define NCHUNKS   (BATCH / MCHUNK)             /* 8 */
#define LDSS      264                          /* 256 + 8 bf16 pad */

#define SM_A      0
#define SM_B      (MCHUNK * LDSS * 2)                 /* 67584 */
#define SM_RED_M  (SM_B + NTILE * LDSS * 2)           /* 135168 */
#define SM_RED_S  (SM_RED_M + 4 * 128 * 4)
#define SMEM_BYTES (SM_RED_S + 4 * 128 * 4 + 64)

__device__ __nv_bfloat16 g_a_bf16[BATCH * NF];
__device__ float g_pm[(size_t)NBLK * BATCH];
__device__ float g_ps[(size_t)NBLK * BATCH];
__device__ float g_tlogit[BATCH];
__device__ float g_rownll[BATCH];
__device__ int   g_tstride;

// ---------------------------------------------------------------- helpers
__device__ __forceinline__ uint32_t sptr(const void* p) {
    return (uint32_t)__cvta_generic_to_shared(p);
}
__device__ __forceinline__ void ldsm4(uint32_t addr, uint32_t& r0, uint32_t& r1,
                                      uint32_t& r2, uint32_t& r3) {
    asm volatile("ldmatrix.sync.aligned.m8n8.x4.shared.b16 {%0,%1,%2,%3}, [%4];"
                 : "=r"(r0), "=r"(r1), "=r"(r2), "=r"(r3) : "r"(addr));
}
__device__ __forceinline__ void mma16816(float c[4], const uint32_t a[4],
                                         uint32_t b0, uint32_t b1) {
    asm volatile(
        "mma.sync.aligned.m16n8k16.row.col.f32.bf16.bf16.f32 "
        "{%0,%1,%2,%3},{%4,%5,%6,%7},{%8,%9},{%0,%1,%2,%3};"
        : "+f"(c[0]), "+f"(c[1]), "+f"(c[2]), "+f"(c[3])
        : "r"(a[0]), "r"(a[1]), "r"(a[2]), "r"(a[3]), "r"(b0), "r"(b1));
}

// ---------------------------------------------------------------- prep kernels
__global__ void prep_kernel(const float* __restrict__ a) {
    int i = blockIdx.x * blockDim.x + threadIdx.x;
    if (i < BATCH * NF) g_a_bf16[i] = __float2bfloat16(a[i]);
}

__global__ void detect_kernel(const int* __restrict__ t32) {
    if (threadIdx.x == 0 && blockIdx.x == 0) {
        int s = 2;
        for (int i = 1; i < 512; i += 2)
            if (t32[i] != 0) { s = 1; break; }
        g_tstride = s;
    }
}

__global__ void tlogit_kernel(const float* __restrict__ a,
                              const int* __restrict__ t32,
                              const float* __restrict__ f) {
    int row = blockIdx.x;
    int tid = threadIdx.x;  // 256
    long long tgt = (long long)t32[row * g_tstride];
    float p = a[row * NF + tid] * f[tgt * NF + tid];
    for (int off = 16; off; off >>= 1) p += __shfl_xor_sync(~0u, p, off);
    __shared__ float sm[8];
    if ((tid & 31) == 0) sm[tid >> 5] = p;
    __syncthreads();
    if (tid == 0) {
        float s = 0.f;
        #pragma unroll
        for (int w = 0; w < 8; w++) s += sm[w];
        g_tlogit[row] = s * INV_TEMP;
    }
}

// ---------------------------------------------------------------- fused GEMM + online softmax partials
extern __shared__ char smem_raw[];

__global__ void __launch_bounds__(512, 1) gemm_lse_kernel(const float* __restrict__ feats) {
    __nv_bfloat16* As = (__nv_bfloat16*)(smem_raw + SM_A);   // [128][264]
    __nv_bfloat16* Bs = (__nv_bfloat16*)(smem_raw + SM_B);   // [128][264]
    float* red_m = (float*)(smem_raw + SM_RED_M);            // [4][128]
    float* red_s = (float*)(smem_raw + SM_RED_S);            // [4][128]

    const int tid  = threadIdx.x;
    const int lane = tid & 31, warp = tid >> 5;     // 16 warps
    const int wm = warp & 3, wn = warp >> 2;        // 4x4 warp grid, 32x32 tiles
    const int nbase = blockIdx.x * NTILE;
    const bool full = (nbase + NTILE <= NS);

    // Load feature slab once (fp32 -> bf16)
    for (int i = tid; i < NTILE * (NF / 4); i += 512) {
        int r  = i >> 6;
        int c4 = i & 63;
        int srow = nbase + r;
        float4 v = make_float4(0.f, 0.f, 0.f, 0.f);
        if (srow < NS) v = ((const float4*)feats)[(size_t)srow * (NF / 4) + c4];
        __nv_bfloat162 p0 = __floats2bfloat162_rn(v.x, v.y);
        __nv_bfloat162 p1 = __floats2bfloat162_rn(v.z, v.w);
        uint2 u;
        u.x = *(uint32_t*)&p0;
        u.y = *(uint32_t*)&p1;
        *(uint2*)(Bs + r * LDSS + c4 * 4) = u;
    }

    const int aRow = lane & 15,                       aKo = (lane >> 4) << 3;
    const int bRow = (lane & 7) + ((lane >> 4) << 3), bKo = ((lane >> 3) & 1) << 3;
    const int qr = lane >> 2, qc = lane & 3;

    // Per-warp SMEM byte addresses at kstep 0 (advance +32B per kstep)
    const uint32_t aA0 = sptr(As + (wm * 32 + aRow) * LDSS + aKo);
    const uint32_t aA1 = aA0 + 16 * LDSS * 2;
    const uint32_t bA0 = sptr(Bs + (wn * 32 + bRow) * LDSS + bKo);
    const uint32_t bA1 = bA0 + 16 * LDSS * 2;

    #pragma unroll 1
    for (int mc = 0; mc < NCHUNKS; mc++) {
        __syncthreads();
        for (int i = tid; i < MCHUNK * (NF / 8); i += 512) {
            int r  = i >> 5;
            int c8 = i & 31;
            uint4 v = ((const uint4*)g_a_bf16)[(size_t)(mc * MCHUNK + r) * (NF / 8) + c8];
            *(uint4*)(As + r * LDSS + c8 * 8) = v;
        }
        __syncthreads();

        float acc[2][4][4];
        #pragma unroll
        for (int mf = 0; mf < 2; mf++)
            #pragma unroll
            for (int nf = 0; nf < 4; nf++)
                #pragma unroll
                for (int j = 0; j < 4; j++) acc[mf][nf][j] = 0.f;

        // software-pipelined k loop: double-buffered fragments
        uint32_t af[2][2][4];
        uint32_t bf[2][4][2];
        ldsm4(aA0, af[0][0][0], af[0][0][1], af[0][0][2], af[0][0][3]);
        ldsm4(aA1, af[0][1][0], af[0][1][1], af[0][1][2], af[0][1][3]);
        ldsm4(bA0, bf[0][0][0], bf[0][0][1], bf[0][1][0], bf[0][1][1]);
        ldsm4(bA1, bf[0][2][0], bf[0][2][1], bf[0][3][0], bf[0][3][1]);

        #pragma unroll
        for (int ks = 0; ks < 16; ks++) {
            const int cur = ks & 1, nx = cur ^ 1;
            if (ks < 15) {
                const uint32_t off = (uint32_t)(ks + 1) * 32;
                ldsm4(aA0 + off, af[nx][0][0], af[nx][0][1], af[nx][0][2], af[nx][0][3]);
                ldsm4(aA1 + off, af[nx][1][0], af[nx][1][1], af[nx][1][2], af[nx][1][3]);
                ldsm4(bA0 + off, bf[nx][0][0], bf[nx][0][1], bf[nx][1][0], bf[nx][1][1]);
                ldsm4(bA1 + off, bf[nx][2][0], bf[nx][2][1], bf[nx][3][0], bf[nx][3][1]);
            }
            #pragma unroll
            for (int mf = 0; mf < 2; mf++)
                #pragma unroll
                for (int nf = 0; nf < 4; nf++)
                    mma16816(acc[mf][nf], af[cur][mf], bf[cur][nf][0], bf[cur][nf][1]);
        }

        // per-row online-softmax partials over this warp's 32-col slice
        #pragma unroll
        for (int mf = 0; mf < 2; mf++) {
            #pragma unroll
            for (int hi = 0; hi < 2; hi++) {
                float m = -INFINITY;
                float s = 0.f;
                if (full) {
                    #pragma unroll
                    for (int nf = 0; nf < 4; nf++)
                        #pragma unroll
                        for (int j = 0; j < 2; j++)
                            m = fmaxf(m, acc[mf][nf][hi * 2 + j]);
                    m *= INV_TEMP;
                    m = fmaxf(m, __shfl_xor_sync(~0u, m, 1));
                    m = fmaxf(m, __shfl_xor_sync(~0u, m, 2));
                    #pragma unroll
                    for (int nf = 0; nf < 4; nf++)
                        #pragma unroll
                        for (int j = 0; j < 2; j++)
                            s += __expf(acc[mf][nf][hi * 2 + j] * INV_TEMP - m);
                } else {
                    #pragma unroll
                    for (int nf = 0; nf < 4; nf++)
                        #pragma unroll
                        for (int j = 0; j < 2; j++) {
                            int cg = nbase + wn * 32 + nf * 8 + qc * 2 + j;
                            float v = acc[mf][nf][hi * 2 + j] * INV_TEMP;
                            if (cg < NS) m = fmaxf(m, v);
                        }
                    m = fmaxf(m, __shfl_xor_sync(~0u, m, 1));
                    m = fmaxf(m, __shfl_xor_sync(~0u, m, 2));
                    #pragma unroll
                    for (int nf = 0; nf < 4; nf++)
                        #pragma unroll
                        for (int j = 0; j < 2; j++) {
                            int cg = nbase + wn * 32 + nf * 8 + qc * 2 + j;
                            float v = acc[mf][nf][hi * 2 + j] * INV_TEMP;
                            if (cg < NS) s += __expf(v - m);
                        }
                }
                s += __shfl_xor_sync(~0u, s, 1);
                s += __shfl_xor_sync(~0u, s, 2);
                if (qc == 0) {
                    int rl = wm * 32 + mf * 16 + hi * 8 + qr;
                    red_m[wn * 128 + rl] = m;
                    red_s[wn * 128 + rl] = s;
                }
            }
        }
        __syncthreads();
        if (tid < 128) {
            float M = red_m[tid];
            #pragma unroll
            for (int w = 1; w < 4; w++) M = fmaxf(M, red_m[w * 128 + tid]);
            float S = 0.f;
            #pragma unroll
            for (int w = 0; w < 4; w++)
                S += red_s[w * 128 + tid] * __expf(red_m[w * 128 + tid] - M);
            int grow = mc * MCHUNK + tid;
            g_pm[(size_t)blockIdx.x * BATCH + grow] = M;
            g_ps[(size_t)blockIdx.x * BATCH + grow] = S;
        }
    }
}

// ---------------------------------------------------------------- cross-block LSE merge
__global__ void lse_kernel() {
    int row = blockIdx.x;
    int tid = threadIdx.x;  // 256
    float M = -INFINITY, S = 0.f;
    for (int b = tid; b < NBLK; b += 256) {
        float m = g_pm[(size_t)b * BATCH + row];
        float s = g_ps[(size_t)b * BATCH + row];
        float nM = fmaxf(M, m);
        S = S * __expf(M - nM) + s * __expf(m - nM);
        M = nM;
    }
    for (int off = 16; off; off >>= 1) {
        float m = __shfl_xor_sync(~0u, M, off);
        float s = __shfl_xor_sync(~0u, S, off);
        float nM = fmaxf(M, m);
        S = S * __expf(M - nM) + s * __expf(m - nM);
        M = nM;
    }
    __shared__ float sm[8], ss[8];
    int w = tid >> 5, ln = tid & 31;
    if (ln == 0) { sm[w] = M; ss[w] = S; }
    __syncthreads();
    if (tid == 0) {
        float Mv = sm[0], Sv = ss[0];
        #pragma unroll
        for (int i = 1; i < 8; i++) {
            float m = sm[i], s = ss[i];
            float nM = fmaxf(Mv, m);
            Sv = Sv * __expf(Mv - nM) + s * __expf(m - nM);
            Mv = nM;
        }
        g_rownll[row] = Mv + logf(Sv) - g_tlogit[row];
    }
}

__global__ void mean_kernel(float* __restrict__ out) {
    __shared__ float sm[32];
    int tid = threadIdx.x;  // 1024
    float v = g_rownll[tid];
    for (int off = 16; off; off >>= 1) v += __shfl_xor_sync(~0u, v, off);
    if ((tid & 31) == 0) sm[tid >> 5] = v;
    __syncthreads();
    if (tid < 32) {
        float x = sm[tid];
        for (int off = 16; off; off >>= 1) x += __shfl_xor_sync(~0u, x, off);
        if (tid == 0) out[0] = x / (float)BATCH;
    }
}

// ---------------------------------------------------------------- launch
extern "C" void kernel_launch(void* const* d_in, const int* in_sizes, int n_in,
                              void* d_out, int out_size) {
    const float* a   = (const float*)d_in[0];   // inputs   [1024,256] f32
    const int*   t32 = (const int*)d_in[1];     // targets  [1024] i64/i32
    const float* f   = (const float*)d_in[2];   // features [100000,256] f32
    float* out = (float*)d_out;

    cudaFuncSetAttribute(gemm_lse_kernel,
                         cudaFuncAttributeMaxDynamicSharedMemorySize, SMEM_BYTES);

    prep_kernel<<<(BATCH * NF + 255) / 256, 256>>>(a);
    detect_kernel<<<1, 32>>>(t32);
    tlogit_kernel<<<BATCH, 256>>>(a, t32, f);
    gemm_lse_kernel<<<NBLK, 512, SMEM_BYTES>>>(f);
    lse_kernel<<<BATCH, 256>>>();
    mean_kernel<<<1, 1024>>>(out);
}

// round 5
// speedup vs baseline: 1.2116x; 1.1172x over previous
#include <cuda_runtime.h>
#include <cuda_bf16.h>
#include <math.h>
#include <stdint.h>

#define BATCH     1024
#define NF        256
#define NS        100000
#define INV_TEMP  20.0f
#define NTILE     256
#define NBLK      ((NS + NTILE - 1) / NTILE)   /* 391 */
#define MCHUNK    128
#define NCHUNKS   (BATCH / MCHUNK)             /* 8 */
#define LDSS      264                          /* 256 + 8 bf16 pad */

#define SM_A      0
#define SM_B      (MCHUNK * LDSS * 2)                 /* 67584 */
#define SM_RED_M  (SM_B + NTILE * LDSS * 2)           /* 202752 */
#define SM_RED_S  (SM_RED_M + 4 * 128 * 4)
#define SMEM_BYTES (SM_RED_S + 4 * 128 * 4 + 64)

__device__ __nv_bfloat16 g_a_bf16[BATCH * NF];
__device__ float g_pm[(size_t)NBLK * BATCH];
__device__ float g_ps[(size_t)NBLK * BATCH];
__device__ float g_tlogit[BATCH];
__device__ float g_rownll[BATCH];
__device__ int   g_tstride;

// ---------------------------------------------------------------- helpers
__device__ __forceinline__ uint32_t sptr(const void* p) {
    return (uint32_t)__cvta_generic_to_shared(p);
}
__device__ __forceinline__ void ldsm4(uint32_t addr, uint32_t& r0, uint32_t& r1,
                                      uint32_t& r2, uint32_t& r3) {
    asm volatile("ldmatrix.sync.aligned.m8n8.x4.shared.b16 {%0,%1,%2,%3}, [%4];"
                 : "=r"(r0), "=r"(r1), "=r"(r2), "=r"(r3) : "r"(addr));
}
__device__ __forceinline__ void mma16816(float c[4], const uint32_t a[4],
                                         uint32_t b0, uint32_t b1) {
    asm volatile(
        "mma.sync.aligned.m16n8k16.row.col.f32.bf16.bf16.f32 "
        "{%0,%1,%2,%3},{%4,%5,%6,%7},{%8,%9},{%0,%1,%2,%3};"
        : "+f"(c[0]), "+f"(c[1]), "+f"(c[2]), "+f"(c[3])
        : "r"(a[0]), "r"(a[1]), "r"(a[2]), "r"(a[3]), "r"(b0), "r"(b1));
}

// ---------------------------------------------------------------- prep kernels
__global__ void prep_kernel(const float* __restrict__ a) {
    int i = blockIdx.x * blockDim.x + threadIdx.x;
    if (i < BATCH * NF) g_a_bf16[i] = __float2bfloat16(a[i]);
}

__global__ void detect_kernel(const int* __restrict__ t32) {
    if (threadIdx.x == 0 && blockIdx.x == 0) {
        int s = 2;
        for (int i = 1; i < 512; i += 2)
            if (t32[i] != 0) { s = 1; break; }
        g_tstride = s;
    }
}

__global__ void tlogit_kernel(const float* __restrict__ a,
                              const int* __restrict__ t32,
                              const float* __restrict__ f) {
    int row = blockIdx.x;
    int tid = threadIdx.x;  // 256
    long long tgt = (long long)t32[row * g_tstride];
    float p = a[row * NF + tid] * f[tgt * NF + tid];
    for (int off = 16; off; off >>= 1) p += __shfl_xor_sync(~0u, p, off);
    __shared__ float sm[8];
    if ((tid & 31) == 0) sm[tid >> 5] = p;
    __syncthreads();
    if (tid == 0) {
        float s = 0.f;
        #pragma unroll
        for (int w = 0; w < 8; w++) s += sm[w];
        g_tlogit[row] = s * INV_TEMP;
    }
}

// ---------------------------------------------------------------- fused GEMM + online softmax partials
extern __shared__ char smem_raw[];

__global__ void __launch_bounds__(256, 1) gemm_lse_kernel(const float* __restrict__ feats) {
    __nv_bfloat16* As = (__nv_bfloat16*)(smem_raw + SM_A);   // [128][264]
    __nv_bfloat16* Bs = (__nv_bfloat16*)(smem_raw + SM_B);   // [256][264]
    float* red_m = (float*)(smem_raw + SM_RED_M);            // [4][128]
    float* red_s = (float*)(smem_raw + SM_RED_S);            // [4][128]

    const int tid  = threadIdx.x;
    const int lane = tid & 31, warp = tid >> 5;     // 8 warps
    const int wm = warp & 1, wn = warp >> 1;        // 2x4 warp grid, 64x64 tiles
    const int nbase = blockIdx.x * NTILE;
    const bool full = (nbase + NTILE <= NS);

    // Load feature slab once (fp32 -> bf16): 256 rows
    for (int i = tid; i < NTILE * (NF / 4); i += 256) {
        int r  = i >> 6;
        int c4 = i & 63;
        int srow = nbase + r;
        float4 v = make_float4(0.f, 0.f, 0.f, 0.f);
        if (srow < NS) v = ((const float4*)feats)[(size_t)srow * (NF / 4) + c4];
        __nv_bfloat162 p0 = __floats2bfloat162_rn(v.x, v.y);
        __nv_bfloat162 p1 = __floats2bfloat162_rn(v.z, v.w);
        uint2 u;
        u.x = *(uint32_t*)&p0;
        u.y = *(uint32_t*)&p1;
        *(uint2*)(Bs + r * LDSS + c4 * 4) = u;
    }

    const int aRow = lane & 15,                       aKo = (lane >> 4) << 3;
    const int bRow = (lane & 7) + ((lane >> 4) << 3), bKo = ((lane >> 3) & 1) << 3;
    const int qr = lane >> 2, qc = lane & 3;

    // Per-warp SMEM byte addresses at kstep 0 (advance +32B per kstep)
    uint32_t aAd[4], bAd[4];
    #pragma unroll
    for (int t = 0; t < 4; t++) {
        aAd[t] = sptr(As + (wm * 64 + t * 16 + aRow) * LDSS + aKo);
        bAd[t] = sptr(Bs + (wn * 64 + t * 16 + bRow) * LDSS + bKo);
    }

    #pragma unroll 1
    for (int mc = 0; mc < NCHUNKS; mc++) {
        __syncthreads();
        for (int i = tid; i < MCHUNK * (NF / 8); i += 256) {
            int r  = i >> 5;
            int c8 = i & 31;
            uint4 v = ((const uint4*)g_a_bf16)[(size_t)(mc * MCHUNK + r) * (NF / 8) + c8];
            *(uint4*)(As + r * LDSS + c8 * 8) = v;
        }
        __syncthreads();

        float acc[4][8][4];
        #pragma unroll
        for (int mf = 0; mf < 4; mf++)
            #pragma unroll
            for (int nf = 0; nf < 8; nf++)
                #pragma unroll
                for (int j = 0; j < 4; j++) acc[mf][nf][j] = 0.f;

        uint32_t af[2][4][4];
        uint32_t bf[2][8][2];
        #pragma unroll
        for (int t = 0; t < 4; t++) {
            ldsm4(aAd[t], af[0][t][0], af[0][t][1], af[0][t][2], af[0][t][3]);
            ldsm4(bAd[t], bf[0][2*t][0], bf[0][2*t][1], bf[0][2*t+1][0], bf[0][2*t+1][1]);
        }

        #pragma unroll
        for (int ks = 0; ks < 16; ks++) {
            const int cur = ks & 1, nx = cur ^ 1;
            if (ks < 15) {
                const uint32_t off = (uint32_t)(ks + 1) * 32;
                #pragma unroll
                for (int t = 0; t < 4; t++) {
                    ldsm4(aAd[t] + off, af[nx][t][0], af[nx][t][1], af[nx][t][2], af[nx][t][3]);
                    ldsm4(bAd[t] + off, bf[nx][2*t][0], bf[nx][2*t][1], bf[nx][2*t+1][0], bf[nx][2*t+1][1]);
                }
            }
            #pragma unroll
            for (int mf = 0; mf < 4; mf++)
                #pragma unroll
                for (int nf = 0; nf < 8; nf++)
                    mma16816(acc[mf][nf], af[cur][mf], bf[cur][nf][0], bf[cur][nf][1]);
        }

        // per-row online-softmax partials over this warp's 64-col slice
        #pragma unroll
        for (int mf = 0; mf < 4; mf++) {
            #pragma unroll
            for (int hi = 0; hi < 2; hi++) {
                float m = -INFINITY;
                float s = 0.f;
                if (full) {
                    #pragma unroll
                    for (int nf = 0; nf < 8; nf++)
                        #pragma unroll
                        for (int j = 0; j < 2; j++)
                            m = fmaxf(m, acc[mf][nf][hi * 2 + j]);
                    m *= INV_TEMP;
                    m = fmaxf(m, __shfl_xor_sync(~0u, m, 1));
                    m = fmaxf(m, __shfl_xor_sync(~0u, m, 2));
                    #pragma unroll
                    for (int nf = 0; nf < 8; nf++)
                        #pragma unroll
                        for (int j = 0; j < 2; j++)
                            s += __expf(acc[mf][nf][hi * 2 + j] * INV_TEMP - m);
                } else {
                    #pragma unroll
                    for (int nf = 0; nf < 8; nf++)
                        #pragma unroll
                        for (int j = 0; j < 2; j++) {
                            int cg = nbase + wn * 64 + nf * 8 + qc * 2 + j;
                            float v = acc[mf][nf][hi * 2 + j] * INV_TEMP;
                            if (cg < NS) m = fmaxf(m, v);
                        }
                    m = fmaxf(m, __shfl_xor_sync(~0u, m, 1));
                    m = fmaxf(m, __shfl_xor_sync(~0u, m, 2));
                    #pragma unroll
                    for (int nf = 0; nf < 8; nf++)
                        #pragma unroll
                        for (int j = 0; j < 2; j++) {
                            int cg = nbase + wn * 64 + nf * 8 + qc * 2 + j;
                            float v = acc[mf][nf][hi * 2 + j] * INV_TEMP;
                            if (cg < NS) s += __expf(v - m);
                        }
                }
                s += __shfl_xor_sync(~0u, s, 1);
                s += __shfl_xor_sync(~0u, s, 2);
                if (qc == 0) {
                    int rl = wm * 64 + mf * 16 + hi * 8 + qr;
                    red_m[wn * 128 + rl] = m;
                    red_s[wn * 128 + rl] = s;
                }
            }
        }
        __syncthreads();
        if (tid < 128) {
            float M = red_m[tid];                 // wn=0 slice always valid
            #pragma unroll
            for (int w = 1; w < 4; w++) M = fmaxf(M, red_m[w * 128 + tid]);
            float S = 0.f;
            #pragma unroll
            for (int w = 0; w < 4; w++)
                S += red_s[w * 128 + tid] * __expf(red_m[w * 128 + tid] - M);
            int grow = mc * MCHUNK + tid;
            g_pm[(size_t)blockIdx.x * BATCH + grow] = M;
            g_ps[(size_t)blockIdx.x * BATCH + grow] = S;
        }
    }
}

// ---------------------------------------------------------------- cross-block LSE merge
__global__ void lse_kernel() {
    int row = blockIdx.x;
    int tid = threadIdx.x;  // 256
    float M = -INFINITY, S = 0.f;
    for (int b = tid; b < NBLK; b += 256) {
        float m = g_pm[(size_t)b * BATCH + row];
        float s = g_ps[(size_t)b * BATCH + row];
        float nM = fmaxf(M, m);
        S = S * __expf(M - nM) + s * __expf(m - nM);
        M = nM;
    }
    for (int off = 16; off; off >>= 1) {
        float m = __shfl_xor_sync(~0u, M, off);
        float s = __shfl_xor_sync(~0u, S, off);
        float nM = fmaxf(M, m);
        S = S * __expf(M - nM) + s * __expf(m - nM);
        M = nM;
    }
    __shared__ float sm[8], ss[8];
    int w = tid >> 5, ln = tid & 31;
    if (ln == 0) { sm[w] = M; ss[w] = S; }
    __syncthreads();
    if (tid == 0) {
        float Mv = sm[0], Sv = ss[0];
        #pragma unroll
        for (int i = 1; i < 8; i++) {
            float m = sm[i], s = ss[i];
            float nM = fmaxf(Mv, m);
            Sv = Sv * __expf(Mv - nM) + s * __expf(m - nM);
            Mv = nM;
        }
        g_rownll[row] = Mv + logf(Sv) - g_tlogit[row];
    }
}

__global__ void mean_kernel(float* __restrict__ out) {
    __shared__ float sm[32];
    int tid = threadIdx.x;  // 1024
    float v = g_rownll[tid];
    for (int off = 16; off; off >>= 1) v += __shfl_xor_sync(~0u, v, off);
    if ((tid & 31) == 0) sm[tid >> 5] = v;
    __syncthreads();
    if (tid < 32) {
        float x = sm[tid];
        for (int off = 16; off; off >>= 1) x += __shfl_xor_sync(~0u, x, off);
        if (tid == 0) out[0] = x / (float)BATCH;
    }
}

// ---------------------------------------------------------------- launch
extern "C" void kernel_launch(void* const* d_in, const int* in_sizes, int n_in,
                              void* d_out, int out_size) {
    const float* a   = (const float*)d_in[0];   // inputs   [1024,256] f32
    const int*   t32 = (const int*)d_in[1];     // targets  [1024] i64/i32
    const float* f   = (const float*)d_in[2];   // features [100000,256] f32
    float* out = (float*)d_out;

    cudaFuncSetAttribute(gemm_lse_kernel,
                         cudaFuncAttributeMaxDynamicSharedMemorySize, SMEM_BYTES);

    prep_kernel<<<(BATCH * NF + 255) / 256, 256>>>(a);
    detect_kernel<<<1, 32>>>(t32);
    tlogit_kernel<<<BATCH, 256>>>(a, t32, f);
    gemm_lse_kernel<<<NBLK, 256, SMEM_BYTES>>>(f);
    lse_kernel<<<BATCH, 256>>>();
    mean_kernel<<<1, 1024>>>(out);
}

// round 6
// speedup vs baseline: 1.3204x; 1.0898x over previous
#include <cuda_runtime.h>
#include <cuda_bf16.h>
#include <math.h>
#include <stdint.h>

#define BATCH     1024
#define NF        256
#define NS        100000
#define INV_TEMP  20.0f
#define LOG2E     1.4426950408889634f
#define LN2F      0.6931471805599453f
#define SCALE2    (INV_TEMP * LOG2E)           /* logits in log2 domain */
#define NTILE     256
#define NBLK      ((NS + NTILE - 1) / NTILE)   /* 391 */
#define MCHUNK    128
#define NCHUNKS   (BATCH / MCHUNK)             /* 8 */
#define LDSS      264                          /* 256 + 8 bf16 pad */

#define SM_A      0
#define SM_B      (MCHUNK * LDSS * 2)                 /* 67584 */
#define SM_RED_M  (SM_B + NTILE * LDSS * 2)           /* 202752 */
#define SM_RED_S  (SM_RED_M + 128 * 16 * 4)           /* +8KB */
#define SMEM_BYTES (SM_RED_S + 128 * 16 * 4 + 64)

__device__ __nv_bfloat16 g_a_bf16[BATCH * NF];
__device__ float g_pm[(size_t)NBLK * BATCH];   /* log2-domain max */
__device__ float g_ps[(size_t)NBLK * BATCH];
__device__ float g_tlogit[BATCH];              /* natural-domain */
__device__ float g_rownll[BATCH];
__device__ int   g_tstride;

// ---------------------------------------------------------------- helpers
__device__ __forceinline__ uint32_t sptr(const void* p) {
    return (uint32_t)__cvta_generic_to_shared(p);
}
__device__ __forceinline__ void ldsm4(uint32_t addr, uint32_t& r0, uint32_t& r1,
                                      uint32_t& r2, uint32_t& r3) {
    asm volatile("ldmatrix.sync.aligned.m8n8.x4.shared.b16 {%0,%1,%2,%3}, [%4];"
                 : "=r"(r0), "=r"(r1), "=r"(r2), "=r"(r3) : "r"(addr));
}
__device__ __forceinline__ void mma16816(float c[4], const uint32_t a[4],
                                         uint32_t b0, uint32_t b1) {
    asm volatile(
        "mma.sync.aligned.m16n8k16.row.col.f32.bf16.bf16.f32 "
        "{%0,%1,%2,%3},{%4,%5,%6,%7},{%8,%9},{%0,%1,%2,%3};"
        : "+f"(c[0]), "+f"(c[1]), "+f"(c[2]), "+f"(c[3])
        : "r"(a[0]), "r"(a[1]), "r"(a[2]), "r"(a[3]), "r"(b0), "r"(b1));
}
#define CP_ASYNC16(dst, src) \
    asm volatile("cp.async.cg.shared.global [%0], [%1], 16;" :: "r"(dst), "l"(src) : "memory")
#define CP_COMMIT() asm volatile("cp.async.commit_group;" ::: "memory")
#define CP_WAIT0()  asm volatile("cp.async.wait_group 0;" ::: "memory")

// ---------------------------------------------------------------- prep kernels
__global__ void prep_kernel(const float* __restrict__ a) {
    int i = blockIdx.x * blockDim.x + threadIdx.x;
    if (i < BATCH * NF) g_a_bf16[i] = __float2bfloat16(a[i]);
}

__global__ void detect_kernel(const int* __restrict__ t32) {
    if (threadIdx.x == 0 && blockIdx.x == 0) {
        int s = 2;
        for (int i = 1; i < 512; i += 2)
            if (t32[i] != 0) { s = 1; break; }
        g_tstride = s;
    }
}

__global__ void tlogit_kernel(const float* __restrict__ a,
                              const int* __restrict__ t32,
                              const float* __restrict__ f) {
    int row = blockIdx.x;
    int tid = threadIdx.x;  // 256
    long long tgt = (long long)t32[row * g_tstride];
    float p = a[row * NF + tid] * f[tgt * NF + tid];
    for (int off = 16; off; off >>= 1) p += __shfl_xor_sync(~0u, p, off);
    __shared__ float sm[8];
    if ((tid & 31) == 0) sm[tid >> 5] = p;
    __syncthreads();
    if (tid == 0) {
        float s = 0.f;
        #pragma unroll
        for (int w = 0; w < 8; w++) s += sm[w];
        g_tlogit[row] = s * INV_TEMP;
    }
}

// ---------------------------------------------------------------- fused GEMM + online softmax partials
extern __shared__ char smem_raw[];

__global__ void __launch_bounds__(256, 1) gemm_lse_kernel(const float* __restrict__ feats) {
    __nv_bfloat16* As = (__nv_bfloat16*)(smem_raw + SM_A);   // [128][264]
    __nv_bfloat16* Bs = (__nv_bfloat16*)(smem_raw + SM_B);   // [256][264]
    float* red_m = (float*)(smem_raw + SM_RED_M);            // [128][16]
    float* red_s = (float*)(smem_raw + SM_RED_S);            // [128][16]

    const int tid  = threadIdx.x;
    const int lane = tid & 31, warp = tid >> 5;     // 8 warps
    const int wm = warp & 1, wn = warp >> 1;        // 2x4 warp grid, 64x64 tiles
    const int nbase = blockIdx.x * NTILE;
    const bool full = (nbase + NTILE <= NS);

    // Issue A chunk 0 via cp.async (overlaps with B conversion below)
    {
        const char* src_base = (const char*)g_a_bf16;
        #pragma unroll
        for (int it = 0; it < 16; it++) {
            int i = tid + it * 256;                // i in [0,4096)
            int r = i >> 5, c8 = i & 31;
            CP_ASYNC16(sptr(As + r * LDSS + c8 * 8), src_base + (size_t)r * 512 + c8 * 16);
        }
        CP_COMMIT();
    }

    // Load feature slab once (fp32 -> bf16): 256 rows
    for (int i = tid; i < NTILE * (NF / 4); i += 256) {
        int r  = i >> 6;
        int c4 = i & 63;
        int srow = nbase + r;
        float4 v = make_float4(0.f, 0.f, 0.f, 0.f);
        if (srow < NS) v = ((const float4*)feats)[(size_t)srow * (NF / 4) + c4];
        __nv_bfloat162 p0 = __floats2bfloat162_rn(v.x, v.y);
        __nv_bfloat162 p1 = __floats2bfloat162_rn(v.z, v.w);
        uint2 u;
        u.x = *(uint32_t*)&p0;
        u.y = *(uint32_t*)&p1;
        *(uint2*)(Bs + r * LDSS + c4 * 4) = u;
    }

    const int aRow = lane & 15,                       aKo = (lane >> 4) << 3;
    const int bRow = (lane & 7) + ((lane >> 4) << 3), bKo = ((lane >> 3) & 1) << 3;
    const int qr = lane >> 2, qc = lane & 3;

    uint32_t aAd[4], bAd[4];
    #pragma unroll
    for (int t = 0; t < 4; t++) {
        aAd[t] = sptr(As + (wm * 64 + t * 16 + aRow) * LDSS + aKo);
        bAd[t] = sptr(Bs + (wn * 64 + t * 16 + bRow) * LDSS + bKo);
    }

    CP_WAIT0();
    __syncthreads();

    #pragma unroll 1
    for (int mc = 0; mc < NCHUNKS; mc++) {
        float acc[4][8][4];
        #pragma unroll
        for (int mf = 0; mf < 4; mf++)
            #pragma unroll
            for (int nf = 0; nf < 8; nf++)
                #pragma unroll
                for (int j = 0; j < 4; j++) acc[mf][nf][j] = 0.f;

        uint32_t af[2][4][4];
        uint32_t bf[2][8][2];
        #pragma unroll
        for (int t = 0; t < 4; t++) {
            ldsm4(aAd[t], af[0][t][0], af[0][t][1], af[0][t][2], af[0][t][3]);
            ldsm4(bAd[t], bf[0][2*t][0], bf[0][2*t][1], bf[0][2*t+1][0], bf[0][2*t+1][1]);
        }

        #pragma unroll
        for (int ks = 0; ks < 16; ks++) {
            const int cur = ks & 1, nx = cur ^ 1;
            if (ks < 15) {
                const uint32_t off = (uint32_t)(ks + 1) * 32;
                #pragma unroll
                for (int t = 0; t < 4; t++) {
                    ldsm4(aAd[t] + off, af[nx][t][0], af[nx][t][1], af[nx][t][2], af[nx][t][3]);
                    ldsm4(bAd[t] + off, bf[nx][2*t][0], bf[nx][2*t][1], bf[nx][2*t+1][0], bf[nx][2*t+1][1]);
                }
            }
            #pragma unroll
            for (int mf = 0; mf < 4; mf++)
                #pragma unroll
                for (int nf = 0; nf < 8; nf++)
                    mma16816(acc[mf][nf], af[cur][mf], bf[cur][nf][0], bf[cur][nf][1]);
        }

        __syncthreads();   // all warps done reading As for this chunk

        // Issue A chunk mc+1 into the same buffer; waits after the epilogue.
        if (mc + 1 < NCHUNKS) {
            const char* src_base = (const char*)g_a_bf16 + (size_t)(mc + 1) * 128 * 512;
            #pragma unroll
            for (int it = 0; it < 16; it++) {
                int i = tid + it * 256;
                int r = i >> 5, c8 = i & 31;
                CP_ASYNC16(sptr(As + r * LDSS + c8 * 8), src_base + (size_t)r * 512 + c8 * 16);
            }
            CP_COMMIT();
        }

        // per-quad online-softmax partials (no shfls; merged by tid<128 later)
        #pragma unroll
        for (int mf = 0; mf < 4; mf++) {
            #pragma unroll
            for (int hi = 0; hi < 2; hi++) {
                float m = -INFINITY;
                float s = 0.f;
                if (full) {
                    #pragma unroll
                    for (int nf = 0; nf < 8; nf++)
                        #pragma unroll
                        for (int j = 0; j < 2; j++)
                            m = fmaxf(m, acc[mf][nf][hi * 2 + j]);
                    m *= SCALE2;
                    #pragma unroll
                    for (int nf = 0; nf < 8; nf++)
                        #pragma unroll
                        for (int j = 0; j < 2; j++)
                            s += exp2f(acc[mf][nf][hi * 2 + j] * SCALE2 - m);
                } else {
                    #pragma unroll
                    for (int nf = 0; nf < 8; nf++)
                        #pragma unroll
                        for (int j = 0; j < 2; j++) {
                            int cg = nbase + wn * 64 + nf * 8 + qc * 2 + j;
                            float v = acc[mf][nf][hi * 2 + j] * SCALE2;
                            if (cg < NS) m = fmaxf(m, v);
                        }
                    #pragma unroll
                    for (int nf = 0; nf < 8; nf++)
                        #pragma unroll
                        for (int j = 0; j < 2; j++) {
                            int cg = nbase + wn * 64 + nf * 8 + qc * 2 + j;
                            float v = acc[mf][nf][hi * 2 + j] * SCALE2;
                            if (cg < NS) s += exp2f(v - m);
                        }
                }
                int rl  = wm * 64 + mf * 16 + hi * 8 + qr;
                int col = wn * 4 + qc;
                red_m[rl * 16 + col] = m;
                red_s[rl * 16 + col] = s;
            }
        }

        CP_WAIT0();
        __syncthreads();   // red partials + next A chunk visible

        // merge runs concurrent with the next chunk's k-loop (safe: next red
        // writes happen only after the post-k-loop barrier, which the merge
        // warps reach only after finishing here).
        if (tid < 128) {
            float M = red_m[tid * 16];
            #pragma unroll
            for (int i = 1; i < 16; i++) M = fmaxf(M, red_m[tid * 16 + i]);
            float S = 0.f;
            #pragma unroll
            for (int i = 0; i < 16; i++)
                S += red_s[tid * 16 + i] * exp2f(red_m[tid * 16 + i] - M);
            int grow = mc * MCHUNK + tid;
            g_pm[(size_t)blockIdx.x * BATCH + grow] = M;
            g_ps[(size_t)blockIdx.x * BATCH + grow] = S;
        }
    }
}

// ---------------------------------------------------------------- cross-block LSE merge (log2 domain)
__global__ void lse_kernel() {
    int row = blockIdx.x;
    int tid = threadIdx.x;  // 256
    float M = -INFINITY, S = 0.f;
    for (int b = tid; b < NBLK; b += 256) {
        float m = g_pm[(size_t)b * BATCH + row];
        float s = g_ps[(size_t)b * BATCH + row];
        float nM = fmaxf(M, m);
        S = S * exp2f(M - nM) + s * exp2f(m - nM);
        M = nM;
    }
    for (int off = 16; off; off >>= 1) {
        float m = __shfl_xor_sync(~0u, M, off);
        float s = __shfl_xor_sync(~0u, S, off);
        float nM = fmaxf(M, m);
        S = S * exp2f(M - nM) + s * exp2f(m - nM);
        M = nM;
    }
    __shared__ float sm[8], ss[8];
    int w = tid >> 5, ln = tid & 31;
    if (ln == 0) { sm[w] = M; ss[w] = S; }
    __syncthreads();
    if (tid == 0) {
        float Mv = sm[0], Sv = ss[0];
        #pragma unroll
        for (int i = 1; i < 8; i++) {
            float m = sm[i], s = ss[i];
            float nM = fmaxf(Mv, m);
            Sv = Sv * exp2f(Mv - nM) + s * exp2f(m - nM);
            Mv = nM;
        }
        g_rownll[row] = (Mv + log2f(Sv)) * LN2F - g_tlogit[row];
    }
}

__global__ void mean_kernel(float* __restrict__ out) {
    __shared__ float sm[32];
    int tid = threadIdx.x;  // 1024
    float v = g_rownll[tid];
    for (int off = 16; off; off >>= 1) v += __shfl_xor_sync(~0u, v, off);
    if ((tid & 31) == 0) sm[tid >> 5] = v;
    __syncthreads();
    if (tid < 32) {
        float x = sm[tid];
        for (int off = 16; off; off >>= 1) x += __shfl_xor_sync(~0u, x, off);
        if (tid == 0) out[0] = x / (float)BATCH;
    }
}

// ---------------------------------------------------------------- launch
extern "C" void kernel_launch(void* const* d_in, const int* in_sizes, int n_in,
                              void* d_out, int out_size) {
    const float* a   = (const float*)d_in[0];   // inputs   [1024,256] f32
    const int*   t32 = (const int*)d_in[1];     // targets  [1024] i64/i32
    const float* f   = (const float*)d_in[2];   // features [100000,256] f32
    float* out = (float*)d_out;

    cudaFuncSetAttribute(gemm_lse_kernel,
                         cudaFuncAttributeMaxDynamicSharedMemorySize, SMEM_BYTES);

    prep_kernel<<<(BATCH * NF + 255) / 256, 256>>>(a);
    detect_kernel<<<1, 32>>>(t32);
    tlogit_kernel<<<BATCH, 256>>>(a, t32, f);
    gemm_lse_kernel<<<NBLK, 256, SMEM_BYTES>>>(f);
    lse_kernel<<<BATCH, 256>>>();
    mean_kernel<<<1, 1024>>>(out);
}